// round 10
// baseline (speedup 1.0000x reference)
#include <cuda_runtime.h>

// ForwardKinematics: B=65536, N=24.
// R9 = R8 + sT/sJ overlay: global t overwrites j in place ([i*3+r] slot is
// written at iteration i, after j[i]'s last read; parents come from the
// register ring). Saves 9.7KB/CTA -> 6 CTAs/SM (24 warps, was 16).
// Bank math: R batch stride 220 f -> banks 28b%32 distinct over b=0..7.
//            J batch stride 76 f  -> banks 12b%32 distinct.

#define THREADS 128
#define MB 32            // batches per block (8 per warp)
#define BPW 8            // batches per warp

static constexpr int NJ   = 24;
static constexpr int RSTR = 220;   // 216 + 4 pad floats = 55 x 16B
static constexpr int JSTR = 76;    // 72 + 4 pad = 19 x 16B (joints, then global t)
static constexpr int SMEM_FLOATS = MB * (RSTR + JSTR);
static constexpr int SMEM_BYTES  = SMEM_FLOATS * 4;   // 37888 B -> 6 CTAs/SM

__global__ __launch_bounds__(THREADS)
void fk_kernel(const float* __restrict__ rot,
               const float* __restrict__ jnt,
               float* __restrict__ out_pj,
               float* __restrict__ out_rel)
{
    extern __shared__ float sm[];
    float* sR = sm;                    // [MB][RSTR] local R (read-only after A)
    float* sJ = sR + MB * RSTR;        // [MB][JSTR] joints, overwritten by global t

    const int tid  = threadIdx.x;
    const int warp = tid >> 5;
    const int lane = tid & 31;
    const int wb   = warp * BPW;
    const long long gBatch = (long long)blockIdx.x * MB + wb;

    // ---------------- Phase A: float4 loads -> float4 smem stores ----------------
    {
        float4* sR4 = reinterpret_cast<float4*>(sR);       // batch stride 55 f4
        const float4* rot4 = reinterpret_cast<const float4*>(rot) + gBatch * 54;
        #pragma unroll
        for (int it = 0; it < 14; ++it) {                  // 8*54 = 432 float4
            int idx = lane + it * 32;
            if (idx < BPW * 54) {
                int b = wb + idx / 54, rf = idx % 54;
                sR4[b * 55 + rf] = rot4[idx];
            }
        }
        float4* sJ4 = reinterpret_cast<float4*>(sJ);       // batch stride 19 f4
        const float4* jnt4 = reinterpret_cast<const float4*>(jnt) + gBatch * 18;
        #pragma unroll
        for (int it = 0; it < 5; ++it) {                   // 8*18 = 144 float4
            int idx = lane + it * 32;
            if (idx < BPW * 18) {
                int b = wb + idx / 18, rf = idx % 18;
                sJ4[b * 19 + rf] = jnt4[idx];
            }
        }
    }
    __syncwarp();

    // ------- Phase B: sync-free chain walk; t overwrites j in place -------
    {
        constexpr int PAR[NJ] = {-1,0,0,0,1,2,3,4,5,6,7,8,9,9,9,12,13,14,16,17,18,19,20,21};
        const int  bl     = lane >> 2;          // 0..7 local batch
        const int  b      = wb + bl;
        const int  r      = lane & 3;
        const bool active = (r < 3);
        float ring[6][4];                       // [slot][Rg_r0,Rg_r1,Rg_r2,t_r]
        float jring[6][3];                      // [slot][j0,j1,j2]
        const float* mR = sR + b * RSTR;
        float*       mJ = sJ + b * JSTR;        // read j[i], then write t[i] same slot
        float4* relW = reinterpret_cast<float4*>(out_rel) + (gBatch + bl) * 96;

        #pragma unroll
        for (int i = 0; i < NJ; ++i) {
            float4 v;
            if (active) {
                float row[4];
                const float j0 = mJ[i * 3 + 0];
                const float j1 = mJ[i * 3 + 1];
                const float j2 = mJ[i * 3 + 2];
                if (i == 0) {
                    row[0] = mR[r * 3 + 0];
                    row[1] = mR[r * 3 + 1];
                    row[2] = mR[r * 3 + 2];
                    row[3] = (r == 0) ? j0 : (r == 1) ? j1 : j2;
                } else {
                    const int p  = PAR[i];
                    const int ps = p % 6;
                    const float a0 = ring[ps][0], a1 = ring[ps][1], a2 = ring[ps][2];
                    const float l00 = mR[i*9+0], l01 = mR[i*9+1], l02 = mR[i*9+2];
                    const float l10 = mR[i*9+3], l11 = mR[i*9+4], l12 = mR[i*9+5];
                    const float l20 = mR[i*9+6], l21 = mR[i*9+7], l22 = mR[i*9+8];
                    const float rel0 = j0 - jring[ps][0];
                    const float rel1 = j1 - jring[ps][1];
                    const float rel2 = j2 - jring[ps][2];
                    row[0] = a0 * l00 + a1 * l10 + a2 * l20;
                    row[1] = a0 * l01 + a1 * l11 + a2 * l21;
                    row[2] = a0 * l02 + a1 * l12 + a2 * l22;
                    row[3] = ring[ps][3] + a0 * rel0 + a1 * rel1 + a2 * rel2;
                }
                const int s = i % 6;
                #pragma unroll
                for (int k = 0; k < 4; ++k) ring[s][k] = row[k];
                jring[s][0] = j0; jring[s][1] = j1; jring[s][2] = j2;
                mJ[i * 3 + r] = row[3];                       // t overwrites j (post-read)
                v = make_float4(row[0], row[1], row[2],
                                row[3] - (row[0]*j0 + row[1]*j1 + row[2]*j2));
            } else {
                v = make_float4(0.f, 0.f, 0.f, 1.f);          // bottom row
            }
            relW[i * 4 + r] = v;                              // direct rel store
        }
    }
    __syncwarp();

    // ---------------- Phase C: coalesced posed-joints copy (LDS.128) ----------------
    {
        const float4* sJ4 = reinterpret_cast<const float4*>(sJ);   // now holds global t
        float4* pj4 = reinterpret_cast<float4*>(out_pj) + gBatch * 18;
        #pragma unroll
        for (int it = 0; it < 5; ++it) {                   // 8*18 = 144 float4
            int idx = lane + it * 32;
            if (idx < BPW * 18) {
                int b = wb + idx / 18, rf = idx % 18;
                pj4[idx] = sJ4[b * 19 + rf];
            }
        }
    }
}

extern "C" void kernel_launch(void* const* d_in, const int* in_sizes, int n_in,
                              void* d_out, int out_size)
{
    const float* rot = (const float*)d_in[0];
    const float* jnt = (const float*)d_in[1];
    float* out = (float*)d_out;

    const long long B = 65536;
    float* out_pj  = out;
    float* out_rel = out + (size_t)B * NJ * 3;

    cudaFuncSetAttribute(fk_kernel, cudaFuncAttributeMaxDynamicSharedMemorySize, SMEM_BYTES);

    const int grid = (int)(B / MB);   // 2048 blocks
    fk_kernel<<<grid, THREADS, SMEM_BYTES>>>(rot, jnt, out_pj, out_rel);
}

// round 11
// speedup vs baseline: 1.4532x; 1.4532x over previous
#include <cuda_runtime.h>

// ForwardKinematics: B=65536, N=24.
// R10 = R8 dataflow exactly (read-only sJ, separate sT, jring, direct rel
// STG.128, coalesced phase-C pj copy) with MB 32->16 so smem/CTA = 23.8KB
// -> 7 CTAs/SM -> 28 resident warps (was 16). No buffer aliasing.
// Bank math unchanged: R batch stride 220 f -> banks 28b%32 distinct, b=0..7.
//                      J/T batch stride 76 f -> banks 12b%32 distinct.

#define THREADS 128
#define MB 16            // batches per block (4 per warp)
#define BPW 4            // batches per warp

static constexpr int NJ   = 24;
static constexpr int RSTR = 220;   // 216 + 4 pad floats = 55 x 16B
static constexpr int JSTR = 76;    // 72 + 4 pad = 19 x 16B
static constexpr int TSTR = 76;    // global t rows
static constexpr int SMEM_FLOATS = MB * (RSTR + JSTR + TSTR);
static constexpr int SMEM_BYTES  = SMEM_FLOATS * 4;   // 23808 B -> 7 CTAs/SM

__global__ __launch_bounds__(THREADS, 7)
void fk_kernel(const float* __restrict__ rot,
               const float* __restrict__ jnt,
               float* __restrict__ out_pj,
               float* __restrict__ out_rel)
{
    extern __shared__ float sm[];
    float* sR = sm;                    // [MB][RSTR] local R (read-only after A)
    float* sJ = sR + MB * RSTR;        // [MB][JSTR] joints (read-only after A)
    float* sT = sJ + MB * JSTR;        // [MB][TSTR] global t

    const int tid  = threadIdx.x;
    const int warp = tid >> 5;
    const int lane = tid & 31;
    const int wb   = warp * BPW;
    const long long gBatch = (long long)blockIdx.x * MB + wb;

    // ---------------- Phase A: float4 loads -> float4 smem stores ----------------
    {
        float4* sR4 = reinterpret_cast<float4*>(sR);       // batch stride 55 f4
        const float4* rot4 = reinterpret_cast<const float4*>(rot) + gBatch * 54;
        #pragma unroll
        for (int it = 0; it < 7; ++it) {                   // 4*54 = 216 float4
            int idx = lane + it * 32;
            if (idx < BPW * 54) {
                int b = wb + idx / 54, rf = idx % 54;
                sR4[b * 55 + rf] = rot4[idx];
            }
        }
        float4* sJ4 = reinterpret_cast<float4*>(sJ);       // batch stride 19 f4
        const float4* jnt4 = reinterpret_cast<const float4*>(jnt) + gBatch * 18;
        #pragma unroll
        for (int it = 0; it < 3; ++it) {                   // 4*18 = 72 float4
            int idx = lane + it * 32;
            if (idx < BPW * 18) {
                int b = wb + idx / 18, rf = idx % 18;
                sJ4[b * 19 + rf] = jnt4[idx];
            }
        }
    }
    __syncwarp();

    // ------- Phase B: sync-free chain walk (lanes 0..15; 4 batches x 4 rows) -------
    {
        constexpr int PAR[NJ] = {-1,0,0,0,1,2,3,4,5,6,7,8,9,9,9,12,13,14,16,17,18,19,20,21};
        const int  bl     = lane >> 2;          // 0..7; only 0..3 valid
        const int  b      = wb + bl;
        const int  r      = lane & 3;
        const bool inB    = (bl < BPW);
        const bool active = inB && (r < 3);
        float ring[6][4];                       // [slot][Rg_r0,Rg_r1,Rg_r2,t_r]
        float jring[6][3];                      // [slot][j0,j1,j2]
        const float* mR = sR + b * RSTR;
        const float* mJ = sJ + b * JSTR;
        float*       mT = sT + b * TSTR;
        float4* relW = reinterpret_cast<float4*>(out_rel) + (gBatch + bl) * 96;

        #pragma unroll
        for (int i = 0; i < NJ; ++i) {
            float4 v;
            if (active) {
                float row[4];
                const float j0 = mJ[i * 3 + 0];
                const float j1 = mJ[i * 3 + 1];
                const float j2 = mJ[i * 3 + 2];
                if (i == 0) {
                    row[0] = mR[r * 3 + 0];
                    row[1] = mR[r * 3 + 1];
                    row[2] = mR[r * 3 + 2];
                    row[3] = (r == 0) ? j0 : (r == 1) ? j1 : j2;
                } else {
                    const int p  = PAR[i];
                    const int ps = p % 6;
                    const float a0 = ring[ps][0], a1 = ring[ps][1], a2 = ring[ps][2];
                    const float l00 = mR[i*9+0], l01 = mR[i*9+1], l02 = mR[i*9+2];
                    const float l10 = mR[i*9+3], l11 = mR[i*9+4], l12 = mR[i*9+5];
                    const float l20 = mR[i*9+6], l21 = mR[i*9+7], l22 = mR[i*9+8];
                    const float rel0 = j0 - jring[ps][0];
                    const float rel1 = j1 - jring[ps][1];
                    const float rel2 = j2 - jring[ps][2];
                    row[0] = a0 * l00 + a1 * l10 + a2 * l20;
                    row[1] = a0 * l01 + a1 * l11 + a2 * l21;
                    row[2] = a0 * l02 + a1 * l12 + a2 * l22;
                    row[3] = ring[ps][3] + a0 * rel0 + a1 * rel1 + a2 * rel2;
                }
                const int s = i % 6;
                #pragma unroll
                for (int k = 0; k < 4; ++k) ring[s][k] = row[k];
                jring[s][0] = j0; jring[s][1] = j1; jring[s][2] = j2;
                mT[i * 3 + r] = row[3];                       // for posed_joints
                v = make_float4(row[0], row[1], row[2],
                                row[3] - (row[0]*j0 + row[1]*j1 + row[2]*j2));
            } else {
                v = make_float4(0.f, 0.f, 0.f, 1.f);          // bottom row
            }
            if (inB)
                relW[i * 4 + r] = v;                          // direct rel store
        }
    }
    __syncwarp();

    // ---------------- Phase C: coalesced posed-joints copy (LDS.128) ----------------
    {
        const float4* sT4 = reinterpret_cast<const float4*>(sT);   // batch stride 19 f4
        float4* pj4 = reinterpret_cast<float4*>(out_pj) + gBatch * 18;
        #pragma unroll
        for (int it = 0; it < 3; ++it) {                   // 4*18 = 72 float4
            int idx = lane + it * 32;
            if (idx < BPW * 18) {
                int b = wb + idx / 18, rf = idx % 18;
                pj4[idx] = sT4[b * 19 + rf];
            }
        }
    }
}

extern "C" void kernel_launch(void* const* d_in, const int* in_sizes, int n_in,
                              void* d_out, int out_size)
{
    const float* rot = (const float*)d_in[0];
    const float* jnt = (const float*)d_in[1];
    float* out = (float*)d_out;

    const long long B = 65536;
    float* out_pj  = out;
    float* out_rel = out + (size_t)B * NJ * 3;

    cudaFuncSetAttribute(fk_kernel, cudaFuncAttributeMaxDynamicSharedMemorySize, SMEM_BYTES);

    const int grid = (int)(B / MB);   // 4096 blocks
    fk_kernel<<<grid, THREADS, SMEM_BYTES>>>(rot, jnt, out_pj, out_rel);
}